// round 14
// baseline (speedup 1.0000x reference)
#include <cuda_runtime.h>
#include <cuda_bf16.h>
#include <cstdint>

#define NEL 33554432           // 2*256*16*64*64
#define NSP 65536               // T*W*H

// ---------------- scratch (device globals; no runtime alloc) ----------------
__device__ float g_buf0[NEL];
__device__ float g_buf1[NEL];
__device__ float g_xp[NEL];
__device__ float g_q[16777216];   // B * 128 * 65536
__device__ float g_k[8388608];    // B * 128 * 32768
__device__ float g_v[16777216];   // B * 256 * 32768
__device__ float g_Sp[1048576];   // split-K partials (256 slices * 4096)
__device__ float g_S[4096];       // attn after softmax: B*64*32 max
// per-cell fragment-major packed weights
__device__ __align__(16) uint32_t g_wfh[196608];   // bf16 hi, 3 cells x 512 tiles
__device__ __align__(16) uint32_t g_wfl[196608];   // bf16 lo
__device__ __align__(16) float    g_wft[131072];   // tf32 q/k, 2 cells (W,H)

// ---------------- helpers ----------------
__device__ __forceinline__ float4 ld4(const float* p) {
    return *reinterpret_cast<const float4*>(p);
}
__device__ __forceinline__ float tf32_rna(float x) {
    uint32_t u;
    asm("cvt.rna.tf32.f32 %0, %1;" : "=r"(u) : "f"(x));
    return __uint_as_float(u);
}
__device__ __forceinline__ float4 rna4(float4 x) {
    x.x = tf32_rna(x.x); x.y = tf32_rna(x.y);
    x.z = tf32_rna(x.z); x.w = tf32_rna(x.w);
    return x;
}
__device__ __forceinline__ void split_f4(float4 v, uint2& h, uint2& l) {
    asm("cvt.rn.bf16x2.f32 %0, %1, %2;" : "=r"(h.x) : "f"(v.y), "f"(v.x));
    asm("cvt.rn.bf16x2.f32 %0, %1, %2;" : "=r"(h.y) : "f"(v.w), "f"(v.z));
    float rx = v.x - __uint_as_float(h.x << 16);
    float ry = v.y - __uint_as_float(h.x & 0xffff0000u);
    float rz = v.z - __uint_as_float(h.y << 16);
    float rw = v.w - __uint_as_float(h.y & 0xffff0000u);
    asm("cvt.rn.bf16x2.f32 %0, %1, %2;" : "=r"(l.x) : "f"(ry), "f"(rx));
    asm("cvt.rn.bf16x2.f32 %0, %1, %2;" : "=r"(l.y) : "f"(rw), "f"(rz));
}
__device__ __forceinline__ void split_pair(float a, float b, uint32_t& h, uint32_t& l) {
    asm("cvt.rn.bf16x2.f32 %0, %1, %2;" : "=r"(h) : "f"(b), "f"(a));
    float ra = a - __uint_as_float(h << 16);
    float rb = b - __uint_as_float(h & 0xffff0000u);
    asm("cvt.rn.bf16x2.f32 %0, %1, %2;" : "=r"(l) : "f"(rb), "f"(ra));
}
__device__ __forceinline__ void ldsm4(uint32_t* r, uint32_t a) {
    asm volatile("ldmatrix.sync.aligned.m8n8.x4.shared.b16 {%0,%1,%2,%3}, [%4];"
        : "=r"(r[0]), "=r"(r[1]), "=r"(r[2]), "=r"(r[3]) : "r"(a));
}
__device__ __forceinline__ void ldsm4t(uint32_t* r, uint32_t a) {
    asm volatile("ldmatrix.sync.aligned.m8n8.x4.trans.shared.b16 {%0,%1,%2,%3}, [%4];"
        : "=r"(r[0]), "=r"(r[1]), "=r"(r[2]), "=r"(r[3]) : "r"(a));
}
__device__ __forceinline__ void ldsm2t(uint32_t* r, uint32_t a) {
    asm volatile("ldmatrix.sync.aligned.m8n8.x2.trans.shared.b16 {%0,%1}, [%2];"
        : "=r"(r[0]), "=r"(r[1]) : "r"(a));
}
__device__ __forceinline__ void mma_bf16(float* d, const uint32_t* a, const uint32_t* b) {
    asm volatile("mma.sync.aligned.m16n8k16.row.col.f32.bf16.bf16.f32 "
        "{%0,%1,%2,%3}, {%4,%5,%6,%7}, {%8,%9}, {%0,%1,%2,%3};"
        : "+f"(d[0]), "+f"(d[1]), "+f"(d[2]), "+f"(d[3])
        : "r"(a[0]), "r"(a[1]), "r"(a[2]), "r"(a[3]), "r"(b[0]), "r"(b[1]));
}
__device__ __forceinline__ void mma_tf32(float* d, const float* a, float b0, float b1) {
    asm volatile(
        "mma.sync.aligned.m16n8k8.row.col.f32.tf32.tf32.f32 "
        "{%0,%1,%2,%3}, {%4,%5,%6,%7}, {%8,%9}, {%0,%1,%2,%3};"
        : "+f"(d[0]), "+f"(d[1]), "+f"(d[2]), "+f"(d[3])
        : "r"(__float_as_uint(a[0])), "r"(__float_as_uint(a[1])),
          "r"(__float_as_uint(a[2])), "r"(__float_as_uint(a[3])),
          "r"(__float_as_uint(b0)), "r"(__float_as_uint(b1)));
}

// ---------------- W fragment pre-pack: bf16 hi/lo (all 512 rows) ------------
__global__ __launch_bounds__(256) void wfrag_prep(
    const float* __restrict__ Wq, const float* __restrict__ Wk,
    const float* __restrict__ Wv, uint32_t* __restrict__ wfh,
    uint32_t* __restrict__ wfl)
{
    int idx = blockIdx.x * 256 + threadIdx.x;   // 16384 = 512 tiles * 32 lanes
    int tile = idx >> 5, lane = idx & 31;
    int mtile = tile >> 4, kt = tile & 15;
    int g = lane >> 2, tg = lane & 3;
    int r0 = mtile * 16 + g;
    int c0 = kt * 16 + tg * 2;

    uint32_t h[4], l[4];
#pragma unroll
    for (int j = 0; j < 4; j++) {
        int r = r0 + ((j & 1) ? 8 : 0);
        int c = c0 + ((j & 2) ? 8 : 0);
        const float* Wr;
        if (r < 128)      Wr = Wq + r * 256;
        else if (r < 256) Wr = Wk + (r - 128) * 256;
        else              Wr = Wv + (r - 256) * 256;
        split_pair(Wr[c], Wr[c + 1], h[j], l[j]);
    }
    *(uint4*)&wfh[tile * 128 + lane * 4] = make_uint4(h[0], h[1], h[2], h[3]);
    *(uint4*)&wfl[tile * 128 + lane * 4] = make_uint4(l[0], l[1], l[2], l[3]);
}

// ---------------- W fragment pre-pack: tf32 (q,k rows only) -----------------
__global__ __launch_bounds__(256) void wfrag_tf(
    const float* __restrict__ Wq, const float* __restrict__ Wk,
    float* __restrict__ wft)
{
    int idx = blockIdx.x * 256 + threadIdx.x;   // 8192 = 256 tiles * 32 lanes
    int tile = idx >> 5, lane = idx & 31;
    int mtile = tile >> 4, kt = tile & 15;
    int g = lane >> 2, tg = lane & 3;
    const float* Wr = (mtile < 8) ? Wq : Wk;
    int m0 = (mtile & 7) * 16;

    float out[8];
#pragma unroll
    for (int s = 0; s < 2; s++)
#pragma unroll
        for (int ai = 0; ai < 4; ai++) {
            int m = m0 + g + ((ai & 1) ? 8 : 0);
            int k = kt * 16 + s * 8 + tg + ((ai & 2) ? 4 : 0);
            out[s * 4 + ai] = tf32_rna(Wr[m * 256 + k]);
        }
    *(float4*)&wft[(tile * 32 + lane) * 8]     = make_float4(out[0], out[1], out[2], out[3]);
    *(float4*)&wft[(tile * 32 + lane) * 8 + 4] = make_float4(out[4], out[5], out[6], out[7]);
}

// ---------------- permute H (canonical -> [c][h][w][t]) via smem transpose ---
__global__ __launch_bounds__(256) void permuteH_kernel(
    const float* __restrict__ src, float* __restrict__ dst)
{
    __shared__ float s[16][65];
    int w = blockIdx.x;
    int c = blockIdx.y;
    int b = blockIdx.z;
    size_t base = ((size_t)b * 256 + c) * 65536;
    int tid = threadIdx.x;
    for (int idx = tid; idx < 1024; idx += 256) {
        int t = idx >> 6, h = idx & 63;
        s[t][h] = src[base + (size_t)t * 4096 + w * 64 + h];
    }
    __syncthreads();
    for (int idx = tid; idx < 1024; idx += 256) {
        int h = idx >> 4, t = idx & 15;
        dst[base + (size_t)h * 1024 + w * 16 + t] = s[t][h];
    }
}

// ---------------- bf16 conv GEMM chunk: 32x32 warp tile, 2 A-tiles ----------
template<int NPASS>
__device__ __forceinline__ void conv_chunk(
    int tbase, uint32_t sb, int wn, int r8, int ch,
    const uint4* __restrict__ wfh4, const uint4* __restrict__ wfl4,
    int lane, float acc[2][4][4])
{
    constexpr int PP = 136;
    constexpr int PT = 256 * PP;

    uint4 Ah0 = wfh4[tbase * 32 + lane];
    uint4 Ah1 = wfh4[(tbase + 16) * 32 + lane];
    uint4 Al0, Al1;
    if (NPASS == 3) {
        Al0 = wfl4[tbase * 32 + lane];
        Al1 = wfl4[(tbase + 16) * 32 + lane];
    }
#pragma unroll 1
    for (int kt = 0; kt < 16; kt++) {
        uint4 Ah0c = Ah0, Ah1c = Ah1, Al0c = Al0, Al1c = Al1;
        if (kt < 15) {
            Ah0 = wfh4[(tbase + kt + 1) * 32 + lane];
            Ah1 = wfh4[(tbase + 16 + kt + 1) * 32 + lane];
            if (NPASS == 3) {
                Al0 = wfl4[(tbase + kt + 1) * 32 + lane];
                Al1 = wfl4[(tbase + 16 + kt + 1) * 32 + lane];
            }
        }
        uint32_t Bh[2][4], Bl[2][4];
#pragma unroll
        for (int st = 0; st < 2; st++) {
            uint32_t ba = sb + (((kt * 16 + r8) * PP) + ch + st * 64 + wn * 16) * 2;
            ldsm4t(Bh[st], ba);
            if (NPASS == 3) ldsm4t(Bl[st], ba + PT * 2);
        }
#pragma unroll
        for (int st = 0; st < 2; st++)
#pragma unroll
            for (int sub = 0; sub < 2; sub++) {
                const uint32_t* bh = Bh[st] + 2 * sub;
                float* d0 = acc[0][st * 2 + sub];
                float* d1 = acc[1][st * 2 + sub];
                mma_bf16(d0, (const uint32_t*)&Ah0c, bh);
                mma_bf16(d1, (const uint32_t*)&Ah1c, bh);
                if (NPASS == 3) {
                    const uint32_t* bl = Bl[st] + 2 * sub;
                    mma_bf16(d0, (const uint32_t*)&Ah0c, bl);
                    mma_bf16(d0, (const uint32_t*)&Al0c, bh);
                    mma_bf16(d1, (const uint32_t*)&Ah1c, bl);
                    mma_bf16(d1, (const uint32_t*)&Al1c, bh);
                }
            }
    }
}

// ---------------- tf32 conv GEMM chunk: 32x32 warp tile ---------------------
__device__ __forceinline__ void conv_chunk_tf(
    int tbase, const float* __restrict__ XPT, int wn, int g, int tg,
    const float4* __restrict__ wft4, int lane, float acc[2][4][4])
{
    constexpr int PPT = 136;

#pragma unroll 1
    for (int kt = 0; kt < 16; kt++) {
        float4 A00 = wft4[((tbase + kt) * 32 + lane) * 2];
        float4 A01 = wft4[((tbase + kt) * 32 + lane) * 2 + 1];
        float4 A10 = wft4[((tbase + 16 + kt) * 32 + lane) * 2];
        float4 A11 = wft4[((tbase + 16 + kt) * 32 + lane) * 2 + 1];
        int kb = kt * 16;
#pragma unroll
        for (int st = 0; st < 2; st++)
#pragma unroll
            for (int sub = 0; sub < 2; sub++) {
                int n = st * 64 + wn * 16 + sub * 8 + g;
                float b0 = XPT[(kb + tg) * PPT + n];
                float b1 = XPT[(kb + tg + 4) * PPT + n];
                float b2 = XPT[(kb + 8 + tg) * PPT + n];
                float b3 = XPT[(kb + 8 + tg + 4) * PPT + n];
                float* d0 = acc[0][st * 2 + sub];
                float* d1 = acc[1][st * 2 + sub];
                mma_tf32(d0, (const float*)&A00, b0, b1);
                mma_tf32(d0, (const float*)&A01, b2, b3);
                mma_tf32(d1, (const float*)&A10, b0, b1);
                mma_tf32(d1, (const float*)&A11, b2, b3);
            }
    }
}

// ---------------- shared conv epilogues (32x32 warp tile) -------------------
__device__ __forceinline__ void conv_epi_q(
    float acc[2][4][4], float* qo, const float* bq, int b,
    int wm, int wn, int g, int tg, int qc0, int qc1)
{
    float* outb = qo + (size_t)b * 8388608;
#pragma unroll
    for (int mt = 0; mt < 2; mt++) {
        int r = wm * 32 + mt * 16 + g;
        float b0 = bq[r], b1 = bq[r + 8];
#pragma unroll
        for (int st = 0; st < 2; st++)
#pragma unroll
            for (int sub = 0; sub < 2; sub++) {
                int col = (st ? qc1 : qc0) + wn * 16 + sub * 8 + tg * 2;
                float* a = acc[mt][st * 2 + sub];
                *(float2*)&outb[(size_t)r * 65536 + col] =
                    make_float2(a[0] + b0, a[1] + b0);
                *(float2*)&outb[(size_t)(r + 8) * 65536 + col] =
                    make_float2(a[2] + b1, a[3] + b1);
            }
    }
}
__device__ __forceinline__ void conv_epi_pool(
    float acc[2][4][4], float* outb, const float* bc,
    int wm, int wn, int g, int tg, int n0)
{
#pragma unroll
    for (int mt = 0; mt < 2; mt++) {
        int r = wm * 32 + mt * 16 + g;
        float b0 = bc[r], b1 = bc[r + 8];
#pragma unroll
        for (int sub = 0; sub < 2; sub++) {
            int col = n0 + wn * 16 + sub * 8 + tg * 2;
            float* a0 = acc[mt][sub];
            float* a1 = acc[mt][2 + sub];
            float v00 = fmaxf(a0[0], a1[0]) + b0;
            float v01 = fmaxf(a0[1], a1[1]) + b0;
            float v10 = fmaxf(a0[2], a1[2]) + b1;
            float v11 = fmaxf(a0[3], a1[3]) + b1;
            *(float2*)&outb[(size_t)r * 32768 + col]       = make_float2(v00, v01);
            *(float2*)&outb[(size_t)(r + 8) * 32768 + col] = make_float2(v10, v11);
        }
    }
}

// ---------------- strip-base computation --------------------------------------
template<int MODE, int LOGD>
__device__ __forceinline__ void strip_bases(int n0, int& s0, int& s1, int& qc0, int& qc1) {
    if (MODE == 0) {
        int a2 = n0 >> LOGD;
        int p0 = n0 & ((1 << LOGD) - 1);
        s0 = ((2 * a2) << LOGD) + p0;
        s1 = s0 + (1 << LOGD);
        qc0 = s0; qc1 = s1;
    } else {
        int aa = n0 >> 10;
        int r  = n0 & 1023;
        s0 = (r >> 6) * 4096 + (2 * aa) * 64;
        s1 = s0 + 64;
        qc0 = (2 * aa) * 1024 + r;
        qc1 = qc0 + 1024;
    }
}

// ---------------- cell-T conv: q/k bf16 3-pass, v bf16 1-pass ---------------
template<int MODE, int LOGD>
__global__ __launch_bounds__(512) void conv_fx(
    const float* __restrict__ X,
    const float* __restrict__ bq, const float* __restrict__ bk,
    const float* __restrict__ bv,
    float* __restrict__ qo, float* __restrict__ ko, float* __restrict__ vo,
    const uint32_t* __restrict__ wfh, const uint32_t* __restrict__ wfl)
{
    constexpr int PP = 136;
    constexpr int PT = 256 * PP;

    extern __shared__ char smem_raw[];
    __nv_bfloat16* XPH = reinterpret_cast<__nv_bfloat16*>(smem_raw);
    __nv_bfloat16* XPL = XPH + PT;

    int b  = blockIdx.z;
    int n0 = blockIdx.x * 64;
    const float* Xb = X + (size_t)b * 256 * NSP;

    int tid  = threadIdx.x;
    int lane = tid & 31, warp = tid >> 5;
    int wm = warp & 3, wn = warp >> 2;      // 4 m-groups x 4 n-groups
    int g = lane >> 2, tg = lane & 3;
    int r8 = (lane & 7) + (lane & 8);
    int ch = (lane & 16) >> 1;

    int s0, s1, qc0, qc1;
    strip_bases<MODE, LOGD>(n0, s0, s1, qc0, qc1);

    {
        int prow = tid >> 4;
        int pcol = (tid & 15) * 4;
#pragma unroll
        for (int it = 0; it < 8; it++) {
            int row = it * 32 + prow;
            float4 x0 = ld4(Xb + (size_t)row * NSP + s0 + pcol);
            float4 x1 = ld4(Xb + (size_t)row * NSP + s1 + pcol);
            uint2 h0, l0, h1, l1;
            split_f4(x0, h0, l0);
            split_f4(x1, h1, l1);
            *(uint2*)&XPH[row * PP + pcol]      = h0;
            *(uint2*)&XPL[row * PP + pcol]      = l0;
            *(uint2*)&XPH[row * PP + 64 + pcol] = h1;
            *(uint2*)&XPL[row * PP + 64 + pcol] = l1;
        }
    }
    __syncthreads();

    uint32_t sb = (uint32_t)__cvta_generic_to_shared(XPH);
    const uint4* wfh4 = reinterpret_cast<const uint4*>(wfh);
    const uint4* wfl4 = reinterpret_cast<const uint4*>(wfl);

    float acc[2][4][4];
    {
#pragma unroll
        for (int mt = 0; mt < 2; mt++)
#pragma unroll
            for (int nt = 0; nt < 4; nt++)
#pragma unroll
                for (int r = 0; r < 4; r++) acc[mt][nt][r] = 0.f;
        conv_chunk<3>((0 * 8 + 2 * wm) * 16, sb, wn, r8, ch, wfh4, wfl4, lane, acc);
        conv_epi_q(acc, qo, bq, b, wm, wn, g, tg, qc0, qc1);
    }
    {
#pragma unroll
        for (int mt = 0; mt < 2; mt++)
#pragma unroll
            for (int nt = 0; nt < 4; nt++)
#pragma unroll
                for (int r = 0; r < 4; r++) acc[mt][nt][r] = 0.f;
        conv_chunk<3>((1 * 8 + 2 * wm) * 16, sb, wn, r8, ch, wfh4, wfl4, lane, acc);
        conv_epi_pool(acc, ko + (size_t)b * 4194304, bk, wm, wn, g, tg, n0);
    }
#pragma unroll 1
    for (int mc = 0; mc < 2; mc++) {
#pragma unroll
        for (int mt = 0; mt < 2; mt++)
#pragma unroll
            for (int nt = 0; nt < 4; nt++)
#pragma unroll
                for (int r = 0; r < 4; r++) acc[mt][nt][r] = 0.f;
        if (mc == 0)
            conv_chunk<1>((2 * 8 + 2 * wm) * 16, sb, wn, r8, ch, wfh4, wfl4, lane, acc);
        else
            conv_chunk<1>((3 * 8 + 2 * wm) * 16, sb, wn, r8, ch, wfh4, wfl4, lane, acc);
        conv_epi_pool(acc, vo + (size_t)b * 8388608 + (size_t)mc * 4194304,
                      bv + mc * 128, wm, wn, g, tg, n0);
    }
}

// ---------------- cells W/H conv: q/k tf32 1-pass, v bf16 1-pass ------------
template<int MODE, int LOGD>
__global__ __launch_bounds__(512) void conv_tf(
    const float* __restrict__ X,
    const float* __restrict__ bq, const float* __restrict__ bk,
    const float* __restrict__ bv,
    float* __restrict__ qo, float* __restrict__ ko, float* __restrict__ vo,
    const float* __restrict__ wft, const uint32_t* __restrict__ wfh)
{
    constexpr int PPT = 136;

    extern __shared__ char smem_raw[];
    float* XPT = reinterpret_cast<float*>(smem_raw);               // 256*136 f32
    __nv_bfloat16* XPB = reinterpret_cast<__nv_bfloat16*>(XPT + 256 * PPT);

    int b  = blockIdx.z;
    int n0 = blockIdx.x * 64;
    const float* Xb = X + (size_t)b * 256 * NSP;

    int tid  = threadIdx.x;
    int lane = tid & 31, warp = tid >> 5;
    int wm = warp & 3, wn = warp >> 2;
    int g = lane >> 2, tg = lane & 3;
    int r8 = (lane & 7) + (lane & 8);
    int ch = (lane & 16) >> 1;

    int s0, s1, qc0, qc1;
    strip_bases<MODE, LOGD>(n0, s0, s1, qc0, qc1);

    {
        int prow = tid >> 4;
        int pcol = (tid & 15) * 4;
#pragma unroll
        for (int it = 0; it < 8; it++) {
            int row = it * 32 + prow;
            float4 x0 = ld4(Xb + (size_t)row * NSP + s0 + pcol);
            float4 x1 = ld4(Xb + (size_t)row * NSP + s1 + pcol);
            *(float4*)&XPT[row * PPT + pcol]      = rna4(x0);
            *(float4*)&XPT[row * PPT + 64 + pcol] = rna4(x1);
            uint2 h0, l0, h1, l1;
            split_f4(x0, h0, l0);
            split_f4(x1, h1, l1);
            *(uint2*)&XPB[row * PPT + pcol]      = h0;
            *(uint2*)&XPB[row * PPT + 64 + pcol] = h1;
        }
    }
    __syncthreads();

    uint32_t sbB = (uint32_t)__cvta_generic_to_shared(XPB);
    const float4* wft4 = reinterpret_cast<const float4*>(wft);
    const uint4*  wfh4 = reinterpret_cast<const uint4*>(wfh);

    float acc[2][4][4];
    {
#pragma unroll
        for (int mt = 0; mt < 2; mt++)
#pragma unroll
            for (int nt = 0; nt < 4; nt++)
#pragma unroll
                for (int r = 0; r < 4; r++) acc[mt][nt][r] = 0.f;
        conv_chunk_tf((0 * 8 + 2 * wm) * 16, XPT, wn, g, tg, wft4, lane, acc);
        conv_epi_q(acc, qo, bq, b, wm, wn, g, tg, qc0, qc1);
    }
    {
#pragma unroll
        for (int mt = 0; mt < 2; mt++)
#pragma unroll
            for (int nt = 0; nt < 4; nt++)
#pragma unroll
                for (int r = 0; r < 4; r++) acc[mt][nt][r] = 0.f;
        conv_chunk_tf((1 * 8 + 2 * wm) * 16, XPT, wn, g, tg, wft4, lane, acc);
        conv_epi_pool(acc, ko + (size_t)b * 4194304, bk, wm, wn, g, tg, n0);
    }
#pragma unroll 1
    for (int mc = 0; mc < 2; mc++) {
#pragma unroll
        for (int mt = 0; mt < 2; mt++)
#pragma unroll
            for (int nt = 0; nt < 4; nt++)
#pragma unroll
                for (int r = 0; r < 4; r++) acc[mt][nt][r] = 0.f;
        if (mc == 0)
            conv_chunk<1>((2 * 8 + 2 * wm) * 16, sbB, wn, r8, ch, wfh4, wfh4, lane, acc);
        else
            conv_chunk<1>((3 * 8 + 2 * wm) * 16, sbB, wn, r8, ch, wfh4, wfh4, lane, acc);
        conv_epi_pool(acc, vo + (size_t)b * 8388608 + (size_t)mc * 4194304,
                      bv + mc * 128, wm, wn, g, tg, n0);
    }
}

// ---------------- attention logits: bf16x3 tensor-core streaming GEMM -------
template<int CELL0>
__global__ __launch_bounds__(256) void attn_mma(
    const float* __restrict__ q, const float* __restrict__ k,
    float* __restrict__ Sp)
{
    constexpr int Ac  = CELL0 ? 16 : 64;
    constexpr int A2c = CELL0 ? 8  : 32;
    constexpr int K   = CELL0 ? 524288 : 131072;
    constexpr int KSL = K / 256;
    constexpr int CJ  = CELL0 ? 128 : 64;
    constexpr int NCH = KSL / CJ;
    constexpr int PQ  = CELL0 ? 136 : 72;
    constexpr int PK  = CELL0 ? 8 : 40;
    constexpr int QT  = Ac * PQ;
    constexpr int KT  = CJ * PK;
    constexpr int NQ  = CELL0 ? 2 : 4;
    constexpr int NK  = CELL0 ? 1 : 2;

    extern __shared__ __nv_bfloat16 smb[];
    __nv_bfloat16 *QH = smb, *QL = QH + 2 * QT, *KH = QL + 2 * QT, *KL = KH + 2 * KT;

    int b = blockIdx.y, sl = blockIdx.x;
    const float* qb = q + (size_t)b * Ac * K + (size_t)sl * KSL;
    const float* kb = k + ((size_t)b * K + (size_t)sl * KSL) * A2c;

    int tid = threadIdx.x, lane = tid & 31, warp = tid >> 5;
    int g = lane >> 2, tg = lane & 3;

    float4 qv[NQ], kv[NK];
    auto LOAD = [&](int chk) {
        int j0 = chk * CJ;
#pragma unroll
        for (int l = 0; l < NQ; l++) {
            int idx = tid + 256 * l;
            int row = CELL0 ? (idx >> 5) : (idx >> 4);
            int c   = CELL0 ? ((idx & 31) * 4) : ((idx & 15) * 4);
            qv[l] = ld4(qb + (size_t)row * K + j0 + c);
        }
#pragma unroll
        for (int l = 0; l < NK; l++) {
            int idx = tid + 256 * l;
            int row = CELL0 ? (idx >> 1) : (idx >> 3);
            int c   = CELL0 ? ((idx & 1) * 4) : ((idx & 7) * 4);
            kv[l] = ld4(kb + (size_t)(j0 + row) * A2c + c);
        }
    };
    auto STORE = [&](int bf) {
#pragma unroll
        for (int l = 0; l < NQ; l++) {
            int idx = tid + 256 * l;
            int row = CELL0 ? (idx >> 5) : (idx >> 4);
            int c   = CELL0 ? ((idx & 31) * 4) : ((idx & 15) * 4);
            uint2 h, lo;
            split_f4(qv[l], h, lo);
            int off = bf * QT + row * PQ + c;
            *(uint2*)&QH[off] = h;
            *(uint2*)&QL[off] = lo;
        }
#pragma unroll
        for (int l = 0; l < NK; l++) {
            int idx = tid + 256 * l;
            int row = CELL0 ? (idx >> 1) : (idx >> 3);
            int c   = CELL0 ? ((idx & 1) * 4) : ((idx & 7) * 4);
            uint2 h, lo;
            split_f4(kv[l], h, lo);
            int off = bf * KT + row * PK + c;
            *(uint2*)&KH[off] = h;
            *(uint2*)&KL[off] = lo;
        }
    };

    uint32_t sb = (uint32_t)__cvta_generic_to_shared(smb);
    int r8 = (lane & 7) + (lane & 8);
    int aoe, boe, wm = warp & 3, wn = warp >> 2;
    if (CELL0) {
        aoe = r8 * PQ + ((lane & 16) >> 1) + warp * 16;
        boe = (warp * 16 + (lane & 15)) * PK;
    } else {
        aoe = (wm * 16 + r8) * PQ + ((lane & 16) >> 1);
        boe = r8 * PK + ((lane & 16) >> 1) + wn * 16;
    }
    constexpr int NACC = CELL0 ? 1 : 2;
    float acc[NACC][4];
#pragma unroll
    for (int a = 0; a < NACC; a++)
#pragma unroll
        for (int r = 0; r < 4; r++) acc[a][r] = 0.f;

    LOAD(0);
    STORE(0);
    __syncthreads();

#pragma unroll 1
    for (int chk = 0; chk < NCH; chk++) {
        int cb = chk & 1;
        if (chk < NCH - 1) LOAD(chk + 1);
        uint32_t qh = sb + (cb * QT + aoe) * 2;
        uint32_t ql = qh + 2 * QT * 2;
        uint32_t kh = sb + 4 * QT * 2 + (cb * KT + boe) * 2;
        uint32_t kl = kh + 2 * KT * 2;
        if (CELL0) {
            uint32_t Ah[4], Al[4], Bh[2], Bl[2];
            ldsm4(Ah, qh); ldsm4(Al, ql);
            ldsm2t(Bh, kh); ldsm2t(Bl, kl);
            mma_bf16(acc[0], Ah, Bh);
            mma_bf16(acc[0], Ah, Bl);
            mma_bf16(acc[0], Al, Bh);
        } else {
#pragma unroll
            for (int ks = 0; ks < 4; ks++) {
                uint32_t Ah[4], Al[4], Bh[4], Bl[4];
                ldsm4(Ah, qh + ks * 32);
                ldsm4(Al, ql + ks * 32);
                ldsm4t(Bh, kh + ks * 16 * PK * 2);
                ldsm4t(Bl, kl + ks * 16 * PK * 2);
#pragma unroll
                for (int sub = 0; sub < 2; sub++) {
                    mma_bf16(acc[sub], Ah, Bh + 2 * sub);
                    mma_bf16(acc[sub], Ah, Bl + 2 * sub);
                    mma_bf16(acc[sub], Al, Bh + 2 * sub);
                }
            }
        }
        if (chk < NCH - 1) STORE(1 - cb);
        __syncthreads();
    }

    if (CELL0) {
        float* red = reinterpret_cast<float*>(smb);
        red[warp * 128 + g * 8 + 2 * tg]           = acc[0][0];
        red[warp * 128 + g * 8 + 2 * tg + 1]       = acc[0][1];
        red[warp * 128 + (g + 8) * 8 + 2 * tg]     = acc[0][2];
        red[warp * 128 + (g + 8) * 8 + 2 * tg + 1] = acc[0][3];
        __syncthreads();
        if (tid < 128) {
            float sum = 0.f;
#pragma unroll
            for (int w = 0; w < 8; w++) sum += red[w * 128 + tid];
            Sp[(size_t)sl * 256 + b * 128 + tid] = sum;
        }
    } else {
        size_t base = (size_t)sl * 4096 + b * 2048;
#pragma unroll
        for (int sub = 0; sub < 2; sub++) {
            int s0 = wn * 16 + sub * 8 + 2 * tg;
            int i0 = wm * 16 + g;
            Sp[base + i0 * 32 + s0]           = acc[sub][0];
            Sp[base + i0 * 32 + s0 + 1]       = acc[sub][1];
            Sp[base + (i0 + 8) * 32 + s0]     = acc[sub][2];
            Sp[base + (i0 + 8) * 32 + s0 + 1] = acc[sub][3];
        }
    }
}

// ---------------- reduce partials + softmax: one block per row ---------------
__global__ __launch_bounds__(256) void softmax_reduce(
    const float* __restrict__ Sp, float* __restrict__ S,
    int A2, int rowtot)
{
    __shared__ float red[256];
    int row = blockIdx.x;
    int tid = threadIdx.x;
    int s = tid & (A2 - 1);
    int chunk = tid / A2;
    float v = 0.f;
#pragma unroll 4
    for (int i = 0; i < 32; i++) {
        if (i >= A2) break;
        int sl = chunk * A2 + i;
        v += Sp[(size_t)sl * rowtot + row * A2 + s];
    }
    red[tid] = v;
    __syncthreads();
    for (int off = 128; off >= 32; off >>= 1) {
        if (tid < off) red[tid] += red[tid + off];
        __syncthreads();
    }
    if (tid < A2) {
        float val = 0.f;
        int nch = 32 / A2;
        for (int c = 0; c < nch; c++) val += red[c * A2 + tid];
        unsigned mask = (A2 == 32) ? 0xffffffffu : ((1u << A2) - 1u);
        float vm = val;
        for (int off = A2 >> 1; off; off >>= 1)
            vm = fmaxf(vm, __shfl_xor_sync(mask, vm, off));
        float e = expf(val - vm);
        float sum = e;
        for (int off = A2 >> 1; off; off >>= 1)
            sum += __shfl_xor_sync(mask, sum, off);
        S[row * A2 + tid] = e / sum;
    }
}

// ---------------- o-GEMM + un-permute + residual (cells T, W) ---------------
template<int CELL>
__global__ __launch_bounds__(256) void epilogue_kernel(
    const float* __restrict__ v, const float* __restrict__ S,
    const float* __restrict__ cur, float* __restrict__ outp,
    const float* __restrict__ gammap)
{
    constexpr int A  = (CELL == 0) ? 16 : 64;
    constexpr int A2 = (CELL == 0) ? 8 : 32;
    constexpr int d  = (CELL == 0) ? 4096 : 1024;

    int b = blockIdx.y;
    __shared__ float attnS[A * A2];
    int tid = threadIdx.x;
    for (int idx = tid; idx < A * A2; idx += 256)
        attnS[idx] = S[b * A * A2 + idx];
    __syncthreads();

    float g = gammap[0];
    int x = blockIdx.x * 256 + tid;

    const float4* vr4 = reinterpret_cast<const float4*>(
        v + (size_t)b * 8388608 + (size_t)x * A2);
    float vv[A2];
#pragma unroll
    for (int s4 = 0; s4 < A2 / 4; s4++) {
        float4 t = vr4[s4];
        vv[s4 * 4 + 0] = t.x; vv[s4 * 4 + 1] = t.y;
        vv[s4 * 4 + 2] = t.z; vv[s4 * 4 + 3] = t.w;
    }
    int c  = x / d;
    int p  = x % d;
    int p1 = p / 64;
    int p2 = p % 64;
    size_t boff = (size_t)b * 16777216 + (size_t)c * 65536;
    int base, stride;
    if (CELL == 0) { base = p1 * 64   + p2; stride = 4096; }
    else           { base = p1 * 4096 + p2; stride = 64;   }

#pragma unroll 4
    for (int a = 0; a < A; a++) {
        float o = 0.f;
#pragma unroll
        for (int s = 0; s < A2; s++) o += vv[s] * attnS[a * A2 + s];
        int off = base + a * stride;
        outp[boff + off] = g * o + cur[boff + off];
    }
}

// ---------------- cell-H epilogue: smem transpose, fully coalesced I/O ------
__global__ __launch_bounds__(256) void epilogue2_kernel(
    const float* __restrict__ v, const float* __restrict__ S,
    const float* __restrict__ cur, float* __restrict__ outp,
    const float* __restrict__ gammap)
{
    int b  = blockIdx.y;
    int cp = blockIdx.x;        // c*16 + p1
    int c = cp >> 4, p1 = cp & 15;

    __shared__ float attnS[64 * 33];
    __shared__ float vs[64 * 33];
    __shared__ float os[64 * 65];
    int tid = threadIdx.x;

    for (int i = tid; i < 2048; i += 256)
        attnS[(i >> 5) * 33 + (i & 31)] = S[b * 2048 + i];
    size_t vbase = (size_t)b * 8388608 + ((size_t)c * 1024 + p1 * 64) * 32;
    for (int i = tid; i < 2048; i += 256)
        vs[(i >> 5) * 33 + (i & 31)] = v[vbase + i];
    __syncthreads();

    int p2 = tid & 63;
    int a0 = (tid >> 6) * 16;
    float vv[32];
#pragma unroll
    for (int s = 0; s < 32; s++) vv[s] = vs[p2 * 33 + s];
#pragma unroll
    for (int ai = 0; ai < 16; ai++) {
        int a = a0 + ai;
        float o = 0.f;
#pragma unroll
        for (int s = 0; s < 32; s++) o += vv[s] * attnS[a * 33 + s];
        os[p2 * 65 + a] = o;
    }
    __syncthreads();

    float g = gammap[0];
    size_t obase = (size_t)b * 16777216 + (size_t)c * 65536 + (size_t)p1 * 4096;
    for (int i = tid; i < 4096; i += 256)
        outp[obase + i] = g * os[(i >> 6) * 65 + (i & 63)] + cur[obase + i];
}

// ---------------- host orchestration ----------------
extern "C" void kernel_launch(void* const* d_in, const int* in_sizes, int n_in,
                              void* d_out, int out_size)
{
    const float* x  = (const float*)d_in[0];
    const float* Wq = (const float*)d_in[1];
    const float* bq = (const float*)d_in[2];
    const float* Wk = (const float*)d_in[3];
    const float* bk = (const float*)d_in[4];
    const float* Wv = (const float*)d_in[5];
    const float* bv = (const float*)d_in[6];
    const float* gm = (const float*)d_in[7];
    float* out = (float*)d_out;

    float *buf0, *buf1, *xp, *q, *k, *v, *Sp, *S, *wft;
    uint32_t *wfh, *wfl;
    cudaGetSymbolAddress((void**)&buf0, g_buf0);
    cudaGetSymbolAddress((void**)&buf1, g_buf1);
    cudaGetSymbolAddress((void**)&xp,   g_xp);
    cudaGetSymbolAddress((void**)&q,    g_q);
    cudaGetSymbolAddress((void**)&k,    g_k);
    cudaGetSymbolAddress((void**)&v,    g_v);
    cudaGetSymbolAddress((void**)&Sp,   g_Sp);
    cudaGetSymbolAddress((void**)&S,    g_S);
    cudaGetSymbolAddress((void**)&wfh,  g_wfh);
    cudaGetSymbolAddress((void**)&wfl,  g_wfl);
    cudaGetSymbolAddress((void**)&wft,  g_wft);

    const int SM_CF = 2 * 256 * 136 * 2;                               // 139264
    const int SM_TF = 256 * 136 * 4 + 256 * 136 * 2;                   // 208896
    const int SM_A0 = (2 * 2176 + 2 * 2176 + 2 * 1024 + 2 * 1024) * 2; // 25600
    const int SM_A1 = (2 * 4608 + 2 * 4608 + 2 * 2560 + 2 * 2560) * 2; // 57344

    cudaFuncSetAttribute(conv_fx<0,12>, cudaFuncAttributeMaxDynamicSharedMemorySize, SM_CF);
    cudaFuncSetAttribute(conv_tf<1,10>, cudaFuncAttributeMaxDynamicSharedMemorySize, SM_TF);
    cudaFuncSetAttribute(conv_tf<0,10>, cudaFuncAttributeMaxDynamicSharedMemorySize, SM_TF);
    cudaFuncSetAttribute(attn_mma<1>, cudaFuncAttributeMaxDynamicSharedMemorySize, SM_A0);
    cudaFuncSetAttribute(attn_mma<0>, cudaFuncAttributeMaxDynamicSharedMemorySize, SM_A1);

    // ---- all weight preprocessing upfront ----
    wfrag_prep<<<64, 256>>>(Wq, Wk, Wv, wfh, wfl);
    wfrag_prep<<<64, 256>>>(Wq + 32768, Wk + 32768, Wv + 65536,
                            wfh + 65536, wfl + 65536);
    wfrag_prep<<<64, 256>>>(Wq + 65536, Wk + 65536, Wv + 131072,
                            wfh + 131072, wfl + 131072);
    wfrag_tf<<<32, 256>>>(Wq + 32768, Wk + 32768, wft);
    wfrag_tf<<<32, 256>>>(Wq + 65536, Wk + 65536, wft + 65536);

    // ================= cell 0 : attention over T (bf16x3 q/k, identity) ======
    {
        conv_fx<0,12><<<dim3(512, 1, 2), 512, SM_CF>>>(
            x, bq, bk, bv, q, k, v, wfh, wfl);
        attn_mma<1><<<dim3(256, 2), 256, SM_A0>>>(q, k, Sp);
        softmax_reduce<<<32, 256>>>(Sp, S, 8, 256);
        epilogue_kernel<0><<<dim3(4096, 2), 256>>>(v, S, x, buf0, gm + 0);
    }
    // ================= cell 1 : attention over W (tf32 q/k, fused permute) ===
    {
        conv_tf<1,10><<<dim3(512, 1, 2), 512, SM_TF>>>(
            buf0, bq + 128, bk + 128, bv + 256, q, k, v, wft, wfh + 65536);
        attn_mma<0><<<dim3(256, 2), 256, SM_A1>>>(q, k, Sp);
        softmax_reduce<<<128, 256>>>(Sp, S, 32, 4096);
        epilogue_kernel<1><<<dim3(1024, 2), 256>>>(v, S, buf0, buf1, gm + 1);
    }
    // ================= cell 2 : attention over H (tf32 q/k) ==================
    {
        permuteH_kernel<<<dim3(64, 256, 2), 256>>>(buf1, xp);
        conv_tf<0,10><<<dim3(512, 1, 2), 512, SM_TF>>>(
            xp, bq + 256, bk + 256, bv + 512, q, k, v, wft + 65536, wfh + 131072);
        attn_mma<0><<<dim3(256, 2), 256, SM_A1>>>(q, k, Sp);
        softmax_reduce<<<128, 256>>>(Sp, S, 32, 4096);
        epilogue2_kernel<<<dim3(4096, 2), 256>>>(v, S, buf1, out, gm + 2);
    }
}

// round 15
// speedup vs baseline: 1.0282x; 1.0282x over previous
#include <cuda_runtime.h>
#include <cuda_bf16.h>
#include <cstdint>

#define NEL 33554432           // 2*256*16*64*64
#define NSP 65536               // T*W*H

// ---------------- scratch (device globals; no runtime alloc) ----------------
__device__ float g_buf0[NEL];
__device__ float g_buf1[NEL];
__device__ float g_xp[NEL];
__device__ float g_q[16777216];   // B * 128 * 65536
__device__ float g_k[8388608];    // B * 128 * 32768
__device__ float g_v[16777216];   // B * 256 * 32768
__device__ float g_Sp[1048576];   // split-K partials (256 slices * 4096)
__device__ float g_S[4096];       // attn after softmax: B*64*32 max
// per-cell fragment-major packed weights
__device__ __align__(16) uint32_t g_wfh[196608];   // bf16 hi, 3 cells x 512 tiles
__device__ __align__(16) uint32_t g_wfl[196608];   // bf16 lo
__device__ __align__(16) float    g_wft[131072];   // tf32 q/k, 2 cells (W,H)

// ---------------- helpers ----------------
__device__ __forceinline__ float4 ld4(const float* p) {
    return *reinterpret_cast<const float4*>(p);
}
__device__ __forceinline__ float tf32_rna(float x) {
    uint32_t u;
    asm("cvt.rna.tf32.f32 %0, %1;" : "=r"(u) : "f"(x));
    return __uint_as_float(u);
}
__device__ __forceinline__ float4 rna4(float4 x) {
    x.x = tf32_rna(x.x); x.y = tf32_rna(x.y);
    x.z = tf32_rna(x.z); x.w = tf32_rna(x.w);
    return x;
}
__device__ __forceinline__ void split_f4(float4 v, uint2& h, uint2& l) {
    asm("cvt.rn.bf16x2.f32 %0, %1, %2;" : "=r"(h.x) : "f"(v.y), "f"(v.x));
    asm("cvt.rn.bf16x2.f32 %0, %1, %2;" : "=r"(h.y) : "f"(v.w), "f"(v.z));
    float rx = v.x - __uint_as_float(h.x << 16);
    float ry = v.y - __uint_as_float(h.x & 0xffff0000u);
    float rz = v.z - __uint_as_float(h.y << 16);
    float rw = v.w - __uint_as_float(h.y & 0xffff0000u);
    asm("cvt.rn.bf16x2.f32 %0, %1, %2;" : "=r"(l.x) : "f"(ry), "f"(rx));
    asm("cvt.rn.bf16x2.f32 %0, %1, %2;" : "=r"(l.y) : "f"(rw), "f"(rz));
}
__device__ __forceinline__ void split_pair(float a, float b, uint32_t& h, uint32_t& l) {
    asm("cvt.rn.bf16x2.f32 %0, %1, %2;" : "=r"(h) : "f"(b), "f"(a));
    float ra = a - __uint_as_float(h << 16);
    float rb = b - __uint_as_float(h & 0xffff0000u);
    asm("cvt.rn.bf16x2.f32 %0, %1, %2;" : "=r"(l) : "f"(rb), "f"(ra));
}
__device__ __forceinline__ void ldsm4(uint32_t* r, uint32_t a) {
    asm volatile("ldmatrix.sync.aligned.m8n8.x4.shared.b16 {%0,%1,%2,%3}, [%4];"
        : "=r"(r[0]), "=r"(r[1]), "=r"(r[2]), "=r"(r[3]) : "r"(a));
}
__device__ __forceinline__ void ldsm4t(uint32_t* r, uint32_t a) {
    asm volatile("ldmatrix.sync.aligned.m8n8.x4.trans.shared.b16 {%0,%1,%2,%3}, [%4];"
        : "=r"(r[0]), "=r"(r[1]), "=r"(r[2]), "=r"(r[3]) : "r"(a));
}
__device__ __forceinline__ void ldsm2t(uint32_t* r, uint32_t a) {
    asm volatile("ldmatrix.sync.aligned.m8n8.x2.trans.shared.b16 {%0,%1}, [%2];"
        : "=r"(r[0]), "=r"(r[1]) : "r"(a));
}
__device__ __forceinline__ void mma_bf16(float* d, const uint32_t* a, const uint32_t* b) {
    asm volatile("mma.sync.aligned.m16n8k16.row.col.f32.bf16.bf16.f32 "
        "{%0,%1,%2,%3}, {%4,%5,%6,%7}, {%8,%9}, {%0,%1,%2,%3};"
        : "+f"(d[0]), "+f"(d[1]), "+f"(d[2]), "+f"(d[3])
        : "r"(a[0]), "r"(a[1]), "r"(a[2]), "r"(a[3]), "r"(b[0]), "r"(b[1]));
}
__device__ __forceinline__ void mma_tf32(float* d, const float* a, float b0, float b1) {
    asm volatile(
        "mma.sync.aligned.m16n8k8.row.col.f32.tf32.tf32.f32 "
        "{%0,%1,%2,%3}, {%4,%5,%6,%7}, {%8,%9}, {%0,%1,%2,%3};"
        : "+f"(d[0]), "+f"(d[1]), "+f"(d[2]), "+f"(d[3])
        : "r"(__float_as_uint(a[0])), "r"(__float_as_uint(a[1])),
          "r"(__float_as_uint(a[2])), "r"(__float_as_uint(a[3])),
          "r"(__float_as_uint(b0)), "r"(__float_as_uint(b1)));
}

// ---------------- W fragment pre-pack: bf16 hi/lo (all 512 rows) ------------
__global__ __launch_bounds__(256) void wfrag_prep(
    const float* __restrict__ Wq, const float* __restrict__ Wk,
    const float* __restrict__ Wv, uint32_t* __restrict__ wfh,
    uint32_t* __restrict__ wfl)
{
    int idx = blockIdx.x * 256 + threadIdx.x;   // 16384 = 512 tiles * 32 lanes
    int tile = idx >> 5, lane = idx & 31;
    int mtile = tile >> 4, kt = tile & 15;
    int g = lane >> 2, tg = lane & 3;
    int r0 = mtile * 16 + g;
    int c0 = kt * 16 + tg * 2;

    uint32_t h[4], l[4];
#pragma unroll
    for (int j = 0; j < 4; j++) {
        int r = r0 + ((j & 1) ? 8 : 0);
        int c = c0 + ((j & 2) ? 8 : 0);
        const float* Wr;
        if (r < 128)      Wr = Wq + r * 256;
        else if (r < 256) Wr = Wk + (r - 128) * 256;
        else              Wr = Wv + (r - 256) * 256;
        split_pair(Wr[c], Wr[c + 1], h[j], l[j]);
    }
    *(uint4*)&wfh[tile * 128 + lane * 4] = make_uint4(h[0], h[1], h[2], h[3]);
    *(uint4*)&wfl[tile * 128 + lane * 4] = make_uint4(l[0], l[1], l[2], l[3]);
}

// ---------------- W fragment pre-pack: tf32 (q,k rows only) -----------------
__global__ __launch_bounds__(256) void wfrag_tf(
    const float* __restrict__ Wq, const float* __restrict__ Wk,
    float* __restrict__ wft)
{
    int idx = blockIdx.x * 256 + threadIdx.x;   // 8192 = 256 tiles * 32 lanes
    int tile = idx >> 5, lane = idx & 31;
    int mtile = tile >> 4, kt = tile & 15;
    int g = lane >> 2, tg = lane & 3;
    const float* Wr = (mtile < 8) ? Wq : Wk;
    int m0 = (mtile & 7) * 16;

    float out[8];
#pragma unroll
    for (int s = 0; s < 2; s++)
#pragma unroll
        for (int ai = 0; ai < 4; ai++) {
            int m = m0 + g + ((ai & 1) ? 8 : 0);
            int k = kt * 16 + s * 8 + tg + ((ai & 2) ? 4 : 0);
            out[s * 4 + ai] = tf32_rna(Wr[m * 256 + k]);
        }
    *(float4*)&wft[(tile * 32 + lane) * 8]     = make_float4(out[0], out[1], out[2], out[3]);
    *(float4*)&wft[(tile * 32 + lane) * 8 + 4] = make_float4(out[4], out[5], out[6], out[7]);
}

// ---------------- permute H (canonical -> [c][h][w][t]) via smem transpose ---
__global__ __launch_bounds__(256) void permuteH_kernel(
    const float* __restrict__ src, float* __restrict__ dst)
{
    __shared__ float s[16][65];
    int w = blockIdx.x;
    int c = blockIdx.y;
    int b = blockIdx.z;
    size_t base = ((size_t)b * 256 + c) * 65536;
    int tid = threadIdx.x;
    for (int idx = tid; idx < 1024; idx += 256) {
        int t = idx >> 6, h = idx & 63;
        s[t][h] = src[base + (size_t)t * 4096 + w * 64 + h];
    }
    __syncthreads();
    for (int idx = tid; idx < 1024; idx += 256) {
        int h = idx >> 4, t = idx & 15;
        dst[base + (size_t)h * 1024 + w * 16 + t] = s[t][h];
    }
}

// ---------------- bf16 conv GEMM chunk (compile-time NPASS, pipelined) ------
template<int NPASS>
__device__ __forceinline__ void conv_chunk(
    int tbase, uint32_t sb, int wn, int r8, int ch,
    const uint4* __restrict__ wfh4, const uint4* __restrict__ wfl4,
    int lane, float acc[8][4])
{
    constexpr int PP = 136;
    constexpr int PT = 256 * PP;

    uint4 Ah = wfh4[tbase * 32 + lane];
    uint4 Al;
    if (NPASS == 3) Al = wfl4[tbase * 32 + lane];

#pragma unroll 1
    for (int kt = 0; kt < 16; kt++) {
        uint4 Ah_c = Ah, Al_c = Al;
        if (kt < 15) {
            Ah = wfh4[(tbase + kt + 1) * 32 + lane];
            if (NPASS == 3) Al = wfl4[(tbase + kt + 1) * 32 + lane];
        }
        uint32_t Bh[4][4], Bl[4][4];
#pragma unroll
        for (int pp = 0; pp < 4; pp++) {
            int pcolp = (pp < 2) ? (wn * 32 + pp * 16)
                                 : (64 + wn * 32 + (pp - 2) * 16);
            uint32_t ba = sb + (((kt * 16 + r8) * PP) + ch + pcolp) * 2;
            ldsm4t(Bh[pp], ba);
            if (NPASS == 3) ldsm4t(Bl[pp], ba + PT * 2);
        }
#pragma unroll
        for (int pp = 0; pp < 4; pp++)
#pragma unroll
            for (int sub = 0; sub < 2; sub++) {
                float* d = acc[pp * 2 + sub];
                mma_bf16(d, (const uint32_t*)&Ah_c, Bh[pp] + 2 * sub);
                if (NPASS == 3) {
                    mma_bf16(d, (const uint32_t*)&Ah_c, Bl[pp] + 2 * sub);
                    mma_bf16(d, (const uint32_t*)&Al_c, Bh[pp] + 2 * sub);
                }
            }
    }
}

// ---------------- tf32 conv GEMM chunk (1-pass, pipelined) ------------------
__device__ __forceinline__ void conv_chunk_tf(
    int tbase, const float* __restrict__ XPT, int wn, int g, int tg,
    const float4* __restrict__ wft4, int lane, float acc[8][4])
{
    constexpr int PPT = 136;

    float4 A0 = wft4[(tbase * 32 + lane) * 2];
    float4 A1 = wft4[(tbase * 32 + lane) * 2 + 1];

#pragma unroll 1
    for (int kt = 0; kt < 16; kt++) {
        float4 A0c = A0, A1c = A1;
        if (kt < 15) {
            A0 = wft4[((tbase + kt + 1) * 32 + lane) * 2];
            A1 = wft4[((tbase + kt + 1) * 32 + lane) * 2 + 1];
        }
        int kb = kt * 16;
#pragma unroll
        for (int pp = 0; pp < 4; pp++) {
            int nb = ((pp < 2) ? (wn * 32 + pp * 16)
                               : (64 + wn * 32 + (pp - 2) * 16)) + g;
#pragma unroll
            for (int sub = 0; sub < 2; sub++) {
                float* d = acc[pp * 2 + sub];
                int n = nb + sub * 8;
                float b0 = XPT[(kb + tg) * PPT + n];
                float b1 = XPT[(kb + tg + 4) * PPT + n];
                mma_tf32(d, (const float*)&A0c, b0, b1);
                float b2 = XPT[(kb + 8 + tg) * PPT + n];
                float b3 = XPT[(kb + 8 + tg + 4) * PPT + n];
                mma_tf32(d, (const float*)&A1c, b2, b3);
            }
        }
    }
}

// ---------------- shared conv epilogues --------------------------------------
__device__ __forceinline__ void conv_epi_q(
    float acc[8][4], float* qo, const float* bq, int b,
    int wm, int wn, int g, int tg, int qc0, int qc1)
{
    float* outb = qo + (size_t)b * 8388608;
    int r = wm * 16 + g;
    float b0 = bq[r], b1 = bq[r + 8];
#pragma unroll
    for (int nt = 0; nt < 8; nt++) {
        int lcol = wn * 32 + ((nt & 3) >> 1) * 16 + (nt & 1) * 8 + tg * 2;
        int col = (nt < 4 ? qc0 : qc1) + lcol;
        *(float2*)&outb[(size_t)r * 65536 + col] =
            make_float2(acc[nt][0] + b0, acc[nt][1] + b0);
        *(float2*)&outb[(size_t)(r + 8) * 65536 + col] =
            make_float2(acc[nt][2] + b1, acc[nt][3] + b1);
    }
}
__device__ __forceinline__ void conv_epi_pool(
    float acc[8][4], float* outb, const float* bc,
    int wm, int wn, int g, int tg, int n0)
{
    int r = wm * 16 + g;
    float b0 = bc[r], b1 = bc[r + 8];
#pragma unroll
    for (int nt = 0; nt < 4; nt++) {
        int col = n0 + wn * 32 + (nt >> 1) * 16 + (nt & 1) * 8 + tg * 2;
        float v00 = fmaxf(acc[nt][0], acc[nt + 4][0]) + b0;
        float v01 = fmaxf(acc[nt][1], acc[nt + 4][1]) + b0;
        float v10 = fmaxf(acc[nt][2], acc[nt + 4][2]) + b1;
        float v11 = fmaxf(acc[nt][3], acc[nt + 4][3]) + b1;
        *(float2*)&outb[(size_t)r * 32768 + col]       = make_float2(v00, v01);
        *(float2*)&outb[(size_t)(r + 8) * 32768 + col] = make_float2(v10, v11);
    }
}

// ---------------- strip-base computation --------------------------------------
template<int MODE, int LOGD>
__device__ __forceinline__ void strip_bases(int n0, int& s0, int& s1, int& qc0, int& qc1) {
    if (MODE == 0) {
        int a2 = n0 >> LOGD;
        int p0 = n0 & ((1 << LOGD) - 1);
        s0 = ((2 * a2) << LOGD) + p0;
        s1 = s0 + (1 << LOGD);
        qc0 = s0; qc1 = s1;
    } else {
        int aa = n0 >> 10;
        int r  = n0 & 1023;
        s0 = (r >> 6) * 4096 + (2 * aa) * 64;
        s1 = s0 + 64;
        qc0 = (2 * aa) * 1024 + r;
        qc1 = qc0 + 1024;
    }
}

// ---------------- cell-T conv: q/k bf16 3-pass, v bf16 1-pass ---------------
template<int MODE, int LOGD>
__global__ __launch_bounds__(512) void conv_fx(
    const float* __restrict__ X,
    const float* __restrict__ bq, const float* __restrict__ bk,
    const float* __restrict__ bv,
    float* __restrict__ qo, float* __restrict__ ko, float* __restrict__ vo,
    const uint32_t* __restrict__ wfh, const uint32_t* __restrict__ wfl)
{
    constexpr int PP = 136;
    constexpr int PT = 256 * PP;

    extern __shared__ char smem_raw[];
    __nv_bfloat16* XPH = reinterpret_cast<__nv_bfloat16*>(smem_raw);
    __nv_bfloat16* XPL = XPH + PT;

    int b  = blockIdx.z;
    int n0 = blockIdx.x * 64;
    const float* Xb = X + (size_t)b * 256 * NSP;

    int tid  = threadIdx.x;
    int lane = tid & 31, warp = tid >> 5;
    int wm = warp & 7, wn = warp >> 3;      // 8 m-groups x 2 n-groups
    int g = lane >> 2, tg = lane & 3;
    int r8 = (lane & 7) + (lane & 8);
    int ch = (lane & 16) >> 1;

    int s0, s1, qc0, qc1;
    strip_bases<MODE, LOGD>(n0, s0, s1, qc0, qc1);

    {
        int prow = tid >> 4;
        int pcol = (tid & 15) * 4;
#pragma unroll
        for (int it = 0; it < 8; it++) {
            int row = it * 32 + prow;
            float4 x0 = ld4(Xb + (size_t)row * NSP + s0 + pcol);
            float4 x1 = ld4(Xb + (size_t)row * NSP + s1 + pcol);
            uint2 h0, l0, h1, l1;
            split_f4(x0, h0, l0);
            split_f4(x1, h1, l1);
            *(uint2*)&XPH[row * PP + pcol]      = h0;
            *(uint2*)&XPL[row * PP + pcol]      = l0;
            *(uint2*)&XPH[row * PP + 64 + pcol] = h1;
            *(uint2*)&XPL[row * PP + 64 + pcol] = l1;
        }
    }
    __syncthreads();

    uint32_t sb = (uint32_t)__cvta_generic_to_shared(XPH);
    const uint4* wfh4 = reinterpret_cast<const uint4*>(wfh);
    const uint4* wfl4 = reinterpret_cast<const uint4*>(wfl);

    float acc[8][4];
    {
#pragma unroll
        for (int nt = 0; nt < 8; nt++)
#pragma unroll
            for (int r = 0; r < 4; r++) acc[nt][r] = 0.f;
        conv_chunk<3>((0 * 8 + wm) * 16, sb, wn, r8, ch, wfh4, wfl4, lane, acc);
        conv_epi_q(acc, qo, bq, b, wm, wn, g, tg, qc0, qc1);
    }
    {
#pragma unroll
        for (int nt = 0; nt < 8; nt++)
#pragma unroll
            for (int r = 0; r < 4; r++) acc[nt][r] = 0.f;
        conv_chunk<3>((1 * 8 + wm) * 16, sb, wn, r8, ch, wfh4, wfl4, lane, acc);
        conv_epi_pool(acc, ko + (size_t)b * 4194304, bk, wm, wn, g, tg, n0);
    }
#pragma unroll 1
    for (int mc = 0; mc < 2; mc++) {
#pragma unroll
        for (int nt = 0; nt < 8; nt++)
#pragma unroll
            for (int r = 0; r < 4; r++) acc[nt][r] = 0.f;
        if (mc == 0)
            conv_chunk<1>((2 * 8 + wm) * 16, sb, wn, r8, ch, wfh4, wfl4, lane, acc);
        else
            conv_chunk<1>((3 * 8 + wm) * 16, sb, wn, r8, ch, wfh4, wfl4, lane, acc);
        conv_epi_pool(acc, vo + (size_t)b * 8388608 + (size_t)mc * 4194304,
                      bv + mc * 128, wm, wn, g, tg, n0);
    }
}

// ---------------- cells W/H conv: q/k tf32 1-pass, v bf16 1-pass ------------
template<int MODE, int LOGD>
__global__ __launch_bounds__(512) void conv_tf(
    const float* __restrict__ X,
    const float* __restrict__ bq, const float* __restrict__ bk,
    const float* __restrict__ bv,
    float* __restrict__ qo, float* __restrict__ ko, float* __restrict__ vo,
    const float* __restrict__ wft, const uint32_t* __restrict__ wfh)
{
    constexpr int PPT = 136;

    extern __shared__ char smem_raw[];
    float* XPT = reinterpret_cast<float*>(smem_raw);               // 256*136 f32
    __nv_bfloat16* XPB = reinterpret_cast<__nv_bfloat16*>(XPT + 256 * PPT);

    int b  = blockIdx.z;
    int n0 = blockIdx.x * 64;
    const float* Xb = X + (size_t)b * 256 * NSP;

    int tid  = threadIdx.x;
    int lane = tid & 31, warp = tid >> 5;
    int wm = warp & 7, wn = warp >> 3;
    int g = lane >> 2, tg = lane & 3;
    int r8 = (lane & 7) + (lane & 8);
    int ch = (lane & 16) >> 1;

    int s0, s1, qc0, qc1;
    strip_bases<MODE, LOGD>(n0, s0, s1, qc0, qc1);

    {
        int prow = tid >> 4;
        int pcol = (tid & 15) * 4;
#pragma unroll
        for (int it = 0; it < 8; it++) {
            int row = it * 32 + prow;
            float4 x0 = ld4(Xb + (size_t)row * NSP + s0 + pcol);
            float4 x1 = ld4(Xb + (size_t)row * NSP + s1 + pcol);
            *(float4*)&XPT[row * PPT + pcol]      = rna4(x0);
            *(float4*)&XPT[row * PPT + 64 + pcol] = rna4(x1);
            uint2 h0, l0, h1, l1;
            split_f4(x0, h0, l0);
            split_f4(x1, h1, l1);
            *(uint2*)&XPB[row * PPT + pcol]      = h0;
            *(uint2*)&XPB[row * PPT + 64 + pcol] = h1;
        }
    }
    __syncthreads();

    uint32_t sbB = (uint32_t)__cvta_generic_to_shared(XPB);
    const float4* wft4 = reinterpret_cast<const float4*>(wft);
    const uint4*  wfh4 = reinterpret_cast<const uint4*>(wfh);

    float acc[8][4];
    {
#pragma unroll
        for (int nt = 0; nt < 8; nt++)
#pragma unroll
            for (int r = 0; r < 4; r++) acc[nt][r] = 0.f;
        conv_chunk_tf((0 * 8 + wm) * 16, XPT, wn, g, tg, wft4, lane, acc);
        conv_epi_q(acc, qo, bq, b, wm, wn, g, tg, qc0, qc1);
    }
    {
#pragma unroll
        for (int nt = 0; nt < 8; nt++)
#pragma unroll
            for (int r = 0; r < 4; r++) acc[nt][r] = 0.f;
        conv_chunk_tf((1 * 8 + wm) * 16, XPT, wn, g, tg, wft4, lane, acc);
        conv_epi_pool(acc, ko + (size_t)b * 4194304, bk, wm, wn, g, tg, n0);
    }
#pragma unroll 1
    for (int mc = 0; mc < 2; mc++) {
#pragma unroll
        for (int nt = 0; nt < 8; nt++)
#pragma unroll
            for (int r = 0; r < 4; r++) acc[nt][r] = 0.f;
        if (mc == 0)
            conv_chunk<1>((2 * 8 + wm) * 16, sbB, wn, r8, ch, wfh4, wfh4, lane, acc);
        else
            conv_chunk<1>((3 * 8 + wm) * 16, sbB, wn, r8, ch, wfh4, wfh4, lane, acc);
        conv_epi_pool(acc, vo + (size_t)b * 8388608 + (size_t)mc * 4194304,
                      bv + mc * 128, wm, wn, g, tg, n0);
    }
}

// ---------------- attention logits: bf16x3 tensor-core streaming GEMM -------
template<int CELL0>
__global__ __launch_bounds__(256) void attn_mma(
    const float* __restrict__ q, const float* __restrict__ k,
    float* __restrict__ Sp)
{
    constexpr int Ac  = CELL0 ? 16 : 64;
    constexpr int A2c = CELL0 ? 8  : 32;
    constexpr int K   = CELL0 ? 524288 : 131072;
    constexpr int KSL = K / 256;
    constexpr int CJ  = CELL0 ? 128 : 64;
    constexpr int NCH = KSL / CJ;
    constexpr int PQ  = CELL0 ? 136 : 72;
    constexpr int PK  = CELL0 ? 8 : 40;
    constexpr int QT  = Ac * PQ;
    constexpr int KT  = CJ * PK;
    constexpr int NQ  = CELL0 ? 2 : 4;
    constexpr int NK  = CELL0 ? 1 : 2;

    extern __shared__ __nv_bfloat16 smb[];
    __nv_bfloat16 *QH = smb, *QL = QH + 2 * QT, *KH = QL + 2 * QT, *KL = KH + 2 * KT;

    int b = blockIdx.y, sl = blockIdx.x;
    const float* qb = q + (size_t)b * Ac * K + (size_t)sl * KSL;
    const float* kb = k + ((size_t)b * K + (size_t)sl * KSL) * A2c;

    int tid = threadIdx.x, lane = tid & 31, warp = tid >> 5;
    int g = lane >> 2, tg = lane & 3;

    float4 qv[NQ], kv[NK];
    auto LOAD = [&](int chk) {
        int j0 = chk * CJ;
#pragma unroll
        for (int l = 0; l < NQ; l++) {
            int idx = tid + 256 * l;
            int row = CELL0 ? (idx >> 5) : (idx >> 4);
            int c   = CELL0 ? ((idx & 31) * 4) : ((idx & 15) * 4);
            qv[l] = ld4(qb + (size_t)row * K + j0 + c);
        }
#pragma unroll
        for (int l = 0; l < NK; l++) {
            int idx = tid + 256 * l;
            int row = CELL0 ? (idx >> 1) : (idx >> 3);
            int c   = CELL0 ? ((idx & 1) * 4) : ((idx & 7) * 4);
            kv[l] = ld4(kb + (size_t)(j0 + row) * A2c + c);
        }
    };
    auto STORE = [&](int bf) {
#pragma unroll
        for (int l = 0; l < NQ; l++) {
            int idx = tid + 256 * l;
            int row = CELL0 ? (idx >> 5) : (idx >> 4);
            int c   = CELL0 ? ((idx & 31) * 4) : ((idx & 15) * 4);
            uint2 h, lo;
            split_f4(qv[l], h, lo);
            int off = bf * QT + row * PQ + c;
            *(uint2*)&QH[off] = h;
            *(uint2*)&QL[off] = lo;
        }
#pragma unroll
        for (int l = 0; l < NK; l++) {
            int idx = tid + 256 * l;
            int row = CELL0 ? (idx >> 1) : (idx >> 3);
            int c   = CELL0 ? ((idx & 1) * 4) : ((idx & 7) * 4);
            uint2 h, lo;
            split_f4(kv[l], h, lo);
            int off = bf * KT + row * PK + c;
            *(uint2*)&KH[off] = h;
            *(uint2*)&KL[off] = lo;
        }
    };

    uint32_t sb = (uint32_t)__cvta_generic_to_shared(smb);
    int r8 = (lane & 7) + (lane & 8);
    int aoe, boe, wm = warp & 3, wn = warp >> 2;
    if (CELL0) {
        aoe = r8 * PQ + ((lane & 16) >> 1) + warp * 16;
        boe = (warp * 16 + (lane & 15)) * PK;
    } else {
        aoe = (wm * 16 + r8) * PQ + ((lane & 16) >> 1);
        boe = r8 * PK + ((lane & 16) >> 1) + wn * 16;
    }
    constexpr int NACC = CELL0 ? 1 : 2;
    float acc[NACC][4];
#pragma unroll
    for (int a = 0; a < NACC; a++)
#pragma unroll
        for (int r = 0; r < 4; r++) acc[a][r] = 0.f;

    LOAD(0);
    STORE(0);
    __syncthreads();

#pragma unroll 1
    for (int chk = 0; chk < NCH; chk++) {
        int cb = chk & 1;
        if (chk < NCH - 1) LOAD(chk + 1);
        uint32_t qh = sb + (cb * QT + aoe) * 2;
        uint32_t ql = qh + 2 * QT * 2;
        uint32_t kh = sb + 4 * QT * 2 + (cb * KT + boe) * 2;
        uint32_t kl = kh + 2 * KT * 2;
        if (CELL0) {
            uint32_t Ah[4], Al[4], Bh[2], Bl[2];
            ldsm4(Ah, qh); ldsm4(Al, ql);
            ldsm2t(Bh, kh); ldsm2t(Bl, kl);
            mma_bf16(acc[0], Ah, Bh);
            mma_bf16(acc[0], Ah, Bl);
            mma_bf16(acc[0], Al, Bh);
        } else {
#pragma unroll
            for (int ks = 0; ks < 4; ks++) {
                uint32_t Ah[4], Al[4], Bh[4], Bl[4];
                ldsm4(Ah, qh + ks * 32);
                ldsm4(Al, ql + ks * 32);
                ldsm4t(Bh, kh + ks * 16 * PK * 2);
                ldsm4t(Bl, kl + ks * 16 * PK * 2);
#pragma unroll
                for (int sub = 0; sub < 2; sub++) {
                    mma_bf16(acc[sub], Ah, Bh + 2 * sub);
                    mma_bf16(acc[sub], Ah, Bl + 2 * sub);
                    mma_bf16(acc[sub], Al, Bh + 2 * sub);
                }
            }
        }
        if (chk < NCH - 1) STORE(1 - cb);
        __syncthreads();
    }

    if (CELL0) {
        float* red = reinterpret_cast<float*>(smb);
        red[warp * 128 + g * 8 + 2 * tg]           = acc[0][0];
        red[warp * 128 + g * 8 + 2 * tg + 1]       = acc[0][1];
        red[warp * 128 + (g + 8) * 8 + 2 * tg]     = acc[0][2];
        red[warp * 128 + (g + 8) * 8 + 2 * tg + 1] = acc[0][3];
        __syncthreads();
        if (tid < 128) {
            float sum = 0.f;
#pragma unroll
            for (int w = 0; w < 8; w++) sum += red[w * 128 + tid];
            Sp[(size_t)sl * 256 + b * 128 + tid] = sum;
        }
    } else {
        size_t base = (size_t)sl * 4096 + b * 2048;
#pragma unroll
        for (int sub = 0; sub < 2; sub++) {
            int s0 = wn * 16 + sub * 8 + 2 * tg;
            int i0 = wm * 16 + g;
            Sp[base + i0 * 32 + s0]           = acc[sub][0];
            Sp[base + i0 * 32 + s0 + 1]       = acc[sub][1];
            Sp[base + (i0 + 8) * 32 + s0]     = acc[sub][2];
            Sp[base + (i0 + 8) * 32 + s0 + 1] = acc[sub][3];
        }
    }
}

// ---------------- reduce partials + softmax: one block per row ---------------
__global__ __launch_bounds__(256) void softmax_reduce(
    const float* __restrict__ Sp, float* __restrict__ S,
    int A2, int rowtot)
{
    __shared__ float red[256];
    int row = blockIdx.x;
    int tid = threadIdx.x;
    int s = tid & (A2 - 1);
    int chunk = tid / A2;
    float v = 0.f;
#pragma unroll 4
    for (int i = 0; i < 32; i++) {
        if (i >= A2) break;
        int sl = chunk * A2 + i;
        v += Sp[(size_t)sl * rowtot + row * A2 + s];
    }
    red[tid] = v;
    __syncthreads();
    for (int off = 128; off >= 32; off >>= 1) {
        if (tid < off) red[tid] += red[tid + off];
        __syncthreads();
    }
    if (tid < A2) {
        float val = 0.f;
        int nch = 32 / A2;
        for (int c = 0; c < nch; c++) val += red[c * A2 + tid];
        unsigned mask = (A2 == 32) ? 0xffffffffu : ((1u << A2) - 1u);
        float vm = val;
        for (int off = A2 >> 1; off; off >>= 1)
            vm = fmaxf(vm, __shfl_xor_sync(mask, vm, off));
        float e = expf(val - vm);
        float sum = e;
        for (int off = A2 >> 1; off; off >>= 1)
            sum += __shfl_xor_sync(mask, sum, off);
        S[row * A2 + tid] = e / sum;
    }
}

// ---------------- o-GEMM + un-permute + residual (cells T, W) ---------------
template<int CELL>
__global__ __launch_bounds__(256) void epilogue_kernel(
    const float* __restrict__ v, const float* __restrict__ S,
    const float* __restrict__ cur, float* __restrict__ outp,
    const float* __restrict__ gammap)
{
    constexpr int A  = (CELL == 0) ? 16 : 64;
    constexpr int A2 = (CELL == 0) ? 8 : 32;
    constexpr int d  = (CELL == 0) ? 4096 : 1024;

    int b = blockIdx.y;
    __shared__ float attnS[A * A2];
    int tid = threadIdx.x;
    for (int idx = tid; idx < A * A2; idx += 256)
        attnS[idx] = S[b * A * A2 + idx];
    __syncthreads();

    float g = gammap[0];
    int x = blockIdx.x * 256 + tid;

    const float4* vr4 = reinterpret_cast<const float4*>(
        v + (size_t)b * 8388608 + (size_t)x * A2);
    float vv[A2];
#pragma unroll
    for (int s4 = 0; s4 < A2 / 4; s4++) {
        float4 t = vr4[s4];
        vv[s4 * 4 + 0] = t.x; vv[s4 * 4 + 1] = t.y;
        vv[s4 * 4 + 2] = t.z; vv[s4 * 4 + 3] = t.w;
    }
    int c  = x / d;
    int p  = x % d;
    int p1 = p / 64;
    int p2 = p % 64;
    size_t boff = (size_t)b * 16777216 + (size_t)c * 65536;
    int base, stride;
    if (CELL == 0) { base = p1 * 64   + p2; stride = 4096; }
    else           { base = p1 * 4096 + p2; stride = 64;   }

#pragma unroll 4
    for (int a = 0; a < A; a++) {
        float o = 0.f;
#pragma unroll
        for (int s = 0; s < A2; s++) o += vv[s] * attnS[a * A2 + s];
        int off = base + a * stride;
        outp[boff + off] = g * o + cur[boff + off];
    }
}

// ---------------- cell-H epilogue: smem transpose, fully coalesced I/O ------
__global__ __launch_bounds__(256) void epilogue2_kernel(
    const float* __restrict__ v, const float* __restrict__ S,
    const float* __restrict__ cur, float* __restrict__ outp,
    const float* __restrict__ gammap)
{
    int b  = blockIdx.y;
    int cp = blockIdx.x;        // c*16 + p1
    int c = cp >> 4, p1 = cp & 15;

    __shared__ float attnS[64 * 33];
    __shared__ float vs[64 * 33];
    __shared__ float os[64 * 65];
    int tid = threadIdx.x;

    for (int i = tid; i < 2048; i += 256)
        attnS[(i >> 5) * 33 + (i & 31)] = S[b * 2048 + i];
    size_t vbase = (size_t)b * 8388608 + ((size_t)c * 1024 + p1 * 64) * 32;
    for (int i = tid; i < 2048; i += 256)
        vs[(i >> 5) * 33 + (i & 31)] = v[vbase + i];
    __syncthreads();

    int p2 = tid & 63;
    int a0 = (tid >> 6) * 16;
    float vv[32];
#pragma unroll
    for (int s = 0; s < 32; s++) vv[s] = vs[p2 * 33 + s];
#pragma unroll
    for (int ai = 0; ai < 16; ai++) {
        int a = a0 + ai;
        float o = 0.f;
#pragma unroll
        for (int s = 0; s < 32; s++) o += vv[s] * attnS[a * 33 + s];
        os[p2 * 65 + a] = o;
    }
    __syncthreads();

    float g = gammap[0];
    size_t obase = (size_t)b * 16777216 + (size_t)c * 65536 + (size_t)p1 * 4096;
    for (int i = tid; i < 4096; i += 256)
        outp[obase + i] = g * os[(i >> 6) * 65 + (i & 63)] + cur[obase + i];
}

// ---------------- host orchestration ----------------
extern "C" void kernel_launch(void* const* d_in, const int* in_sizes, int n_in,
                              void* d_out, int out_size)
{
    const float* x  = (const float*)d_in[0];
    const float* Wq = (const float*)d_in[1];
    const float* bq = (const float*)d_in[2];
    const float* Wk = (const float*)d_in[3];
    const float* bk = (const float*)d_in[4];
    const float* Wv = (const float*)d_in[5];
    const float* bv = (const float*)d_in[6];
    const float* gm = (const float*)d_in[7];
    float* out = (float*)d_out;

    float *buf0, *buf1, *xp, *q, *k, *v, *Sp, *S, *wft;
    uint32_t *wfh, *wfl;
    cudaGetSymbolAddress((void**)&buf0, g_buf0);
    cudaGetSymbolAddress((void**)&buf1, g_buf1);
    cudaGetSymbolAddress((void**)&xp,   g_xp);
    cudaGetSymbolAddress((void**)&q,    g_q);
    cudaGetSymbolAddress((void**)&k,    g_k);
    cudaGetSymbolAddress((void**)&v,    g_v);
    cudaGetSymbolAddress((void**)&Sp,   g_Sp);
    cudaGetSymbolAddress((void**)&S,    g_S);
    cudaGetSymbolAddress((void**)&wfh,  g_wfh);
    cudaGetSymbolAddress((void**)&wfl,  g_wfl);
    cudaGetSymbolAddress((void**)&wft,  g_wft);

    const int SM_CF = 2 * 256 * 136 * 2;                               // 139264
    const int SM_TF = 256 * 136 * 4 + 256 * 136 * 2;                   // 208896
    const int SM_A0 = (2 * 2176 + 2 * 2176 + 2 * 1024 + 2 * 1024) * 2; // 25600
    const int SM_A1 = (2 * 4608 + 2 * 4608 + 2 * 2560 + 2 * 2560) * 2; // 57344

    cudaFuncSetAttribute(conv_fx<0,12>, cudaFuncAttributeMaxDynamicSharedMemorySize, SM_CF);
    cudaFuncSetAttribute(conv_tf<1,10>, cudaFuncAttributeMaxDynamicSharedMemorySize, SM_TF);
    cudaFuncSetAttribute(conv_tf<0,10>, cudaFuncAttributeMaxDynamicSharedMemorySize, SM_TF);
    cudaFuncSetAttribute(attn_mma<1>, cudaFuncAttributeMaxDynamicSharedMemorySize, SM_A0);
    cudaFuncSetAttribute(attn_mma<0>, cudaFuncAttributeMaxDynamicSharedMemorySize, SM_A1);

    // ---- all weight preprocessing upfront ----
    wfrag_prep<<<64, 256>>>(Wq, Wk, Wv, wfh, wfl);
    wfrag_prep<<<64, 256>>>(Wq + 32768, Wk + 32768, Wv + 65536,
                            wfh + 65536, wfl + 65536);
    wfrag_prep<<<64, 256>>>(Wq + 65536, Wk + 65536, Wv + 131072,
                            wfh + 131072, wfl + 131072);
    wfrag_tf<<<32, 256>>>(Wq + 32768, Wk + 32768, wft);
    wfrag_tf<<<32, 256>>>(Wq + 65536, Wk + 65536, wft + 65536);

    // ================= cell 0 : attention over T (bf16x3 q/k, identity) ======
    {
        conv_fx<0,12><<<dim3(512, 1, 2), 512, SM_CF>>>(
            x, bq, bk, bv, q, k, v, wfh, wfl);
        attn_mma<1><<<dim3(256, 2), 256, SM_A0>>>(q, k, Sp);
        softmax_reduce<<<32, 256>>>(Sp, S, 8, 256);
        epilogue_kernel<0><<<dim3(4096, 2), 256>>>(v, S, x, buf0, gm + 0);
    }
    // ================= cell 1 : attention over W (tf32 q/k, fused permute) ===
    {
        conv_tf<1,10><<<dim3(512, 1, 2), 512, SM_TF>>>(
            buf0, bq + 128, bk + 128, bv + 256, q, k, v, wft, wfh + 65536);
        attn_mma<0><<<dim3(256, 2), 256, SM_A1>>>(q, k, Sp);
        softmax_reduce<<<128, 256>>>(Sp, S, 32, 4096);
        epilogue_kernel<1><<<dim3(1024, 2), 256>>>(v, S, buf0, buf1, gm + 1);
    }
    // ================= cell 2 : attention over H (tf32 q/k) ==================
    {
        permuteH_kernel<<<dim3(64, 256, 2), 256>>>(buf1, xp);
        conv_tf<0,10><<<dim3(512, 1, 2), 512, SM_TF>>>(
            xp, bq + 256, bk + 256, bv + 512, q, k, v, wft + 65536, wfh + 131072);
        attn_mma<0><<<dim3(256, 2), 256, SM_A1>>>(q, k, Sp);
        softmax_reduce<<<128, 256>>>(Sp, S, 32, 4096);
        epilogue2_kernel<<<dim3(4096, 2), 256>>>(v, S, buf1, out, gm + 2);
    }
}